// round 3
// baseline (speedup 1.0000x reference)
#include <cuda_runtime.h>
#include <math_constants.h>

// Cumulative max along H for x[B=32, C=1, H=1024, W=2048] fp32.
// One thread owns one float4-wide column (4 consecutive w), scans H
// sequentially. Perfectly coalesced, streaming, single pass:
// 256 MB read + 256 MB write -> HBM-bound.
//
// MLP: batch 8 independent LDG.128 per chunk before the dependent
// fmax+STG chain, giving ~4 KB in flight per warp (~2 MB chip-wide,
// matching the BW*latency product at ~3.5 warps/SM occupancy).

static constexpr int B = 32;
static constexpr int H = 1024;
static constexpr int W = 2048;
static constexpr int W4 = W / 4;          // 512 float4 per row
static constexpr int NCOLS = B * W4;      // 16384 threads
static constexpr int UNROLL = 8;

__global__ void __launch_bounds__(64, 8)
cummax_h_kernel(const float4* __restrict__ x, float4* __restrict__ out) {
    int c = blockIdx.x * blockDim.x + threadIdx.x;   // 0 .. NCOLS-1
    if (c >= NCOLS) return;

    int b  = c >> 9;          // c / 512
    int w4 = c & (W4 - 1);    // c % 512

    const float4* __restrict__ p = x   + (size_t)b * H * W4 + w4;
    float4*       __restrict__ q = out + (size_t)b * H * W4 + w4;

    float4 m = make_float4(-CUDART_INF_F, -CUDART_INF_F,
                           -CUDART_INF_F, -CUDART_INF_F);

    for (int h0 = 0; h0 < H; h0 += UNROLL) {
        float4 v[UNROLL];
        // Batch independent loads: 8 outstanding LDG.128 per thread.
        #pragma unroll
        for (int i = 0; i < UNROLL; i++) {
            v[i] = __ldg(p + (size_t)(h0 + i) * W4);
        }
        // Dependent prefix-max chain + vectorized stores.
        #pragma unroll
        for (int i = 0; i < UNROLL; i++) {
            m.x = fmaxf(m.x, v[i].x);
            m.y = fmaxf(m.y, v[i].y);
            m.z = fmaxf(m.z, v[i].z);
            m.w = fmaxf(m.w, v[i].w);
            q[(size_t)(h0 + i) * W4] = m;
        }
    }
}

extern "C" void kernel_launch(void* const* d_in, const int* in_sizes, int n_in,
                              void* d_out, int out_size) {
    const float4* x   = (const float4*)d_in[0];
    float4*       out = (float4*)d_out;

    // 256 blocks x 64 threads = 16384 threads, one per float4 column.
    cummax_h_kernel<<<NCOLS / 64, 64>>>(x, out);
}

// round 4
// speedup vs baseline: 1.2913x; 1.2913x over previous
#include <cuda_runtime.h>
#include <math_constants.h>

// Cumulative max along H for x[B=32, C=1, H=1024, W=2048] fp32.
// One thread owns one float4 column (4 consecutive w), scans H serially.
// Streaming single pass: 256 MB read + 256 MB write, HBM-bound.
//
// R3: double-buffered software pipeline. Loads for chunk k+1 issue BEFORE
// the dependent fmax/store chain of chunk k, keeping 8-16 LDG.128 in
// flight per thread continuously (~2-4 MB chip-wide, >= BW*latency
// product) instead of draining to 0 every chunk. Streaming ld.cs/st.cs
// hints since no byte is reused.

static constexpr int B = 32;
static constexpr int H = 1024;
static constexpr int W = 2048;
static constexpr int W4 = W / 4;            // 512 float4 per row
static constexpr int NCOLS = B * W4;        // 16384 threads
static constexpr int U = 8;                 // float4 loads per chunk
static constexpr int NCHUNK = H / U;        // 128 chunks (even)

__device__ __forceinline__ float4 ld_stream(const float4* p) {
    return __ldcs(p);
}

__device__ __forceinline__ void st_stream(float4* p, float4 v) {
    __stcs(p, v);
}

__global__ void __launch_bounds__(64)
cummax_h_kernel(const float4* __restrict__ x, float4* __restrict__ out) {
    int c = blockIdx.x * blockDim.x + threadIdx.x;   // 0 .. NCOLS-1

    int b  = c >> 9;          // c / 512
    int w4 = c & (W4 - 1);    // c % 512

    const float4* __restrict__ p = x   + (size_t)b * H * W4 + w4;
    float4*       __restrict__ q = out + (size_t)b * H * W4 + w4;

    float4 m = make_float4(-CUDART_INF_F, -CUDART_INF_F,
                           -CUDART_INF_F, -CUDART_INF_F);

    float4 va[U], vb[U];

    // Prologue: load chunk 0 into va.
    #pragma unroll
    for (int i = 0; i < U; i++)
        va[i] = ld_stream(p + (size_t)i * W4);

    // Main loop: process two chunks per iteration, always prefetching
    // the next chunk before consuming the current one.
    for (int cc = 0; cc < NCHUNK; cc += 2) {
        int hA = cc * U;
        int hB = (cc + 1) * U;
        int hC = (cc + 2) * U;

        // Prefetch chunk cc+1 into vb (NCHUNK even -> always valid).
        #pragma unroll
        for (int i = 0; i < U; i++)
            vb[i] = ld_stream(p + (size_t)(hB + i) * W4);

        // Process chunk cc (va): dependent fmax chain + streaming stores.
        #pragma unroll
        for (int i = 0; i < U; i++) {
            m.x = fmaxf(m.x, va[i].x);
            m.y = fmaxf(m.y, va[i].y);
            m.z = fmaxf(m.z, va[i].z);
            m.w = fmaxf(m.w, va[i].w);
            st_stream(q + (size_t)(hA + i) * W4, m);
        }

        // Prefetch chunk cc+2 into va (guarded for the final iteration).
        if (cc + 2 < NCHUNK) {
            #pragma unroll
            for (int i = 0; i < U; i++)
                va[i] = ld_stream(p + (size_t)(hC + i) * W4);
        }

        // Process chunk cc+1 (vb).
        #pragma unroll
        for (int i = 0; i < U; i++) {
            m.x = fmaxf(m.x, vb[i].x);
            m.y = fmaxf(m.y, vb[i].y);
            m.z = fmaxf(m.z, vb[i].z);
            m.w = fmaxf(m.w, vb[i].w);
            st_stream(q + (size_t)(hB + i) * W4, m);
        }
    }
}

extern "C" void kernel_launch(void* const* d_in, const int* in_sizes, int n_in,
                              void* d_out, int out_size) {
    const float4* x   = (const float4*)d_in[0];
    float4*       out = (float4*)d_out;

    // 256 blocks x 64 threads = 16384 threads, one per float4 column.
    cummax_h_kernel<<<NCOLS / 64, 64>>>(x, out);
}

// round 5
// speedup vs baseline: 1.3859x; 1.0733x over previous
#include <cuda_runtime.h>
#include <math_constants.h>

// Cumulative max along H for x[B=32, C=1, H=1024, W=2048] fp32.
// Single streaming pass: 256 MB read + 256 MB write (the minimum).
//
// R4: float2 per thread (32768 threads, 512 blocks -> ~6.9 warps/SM,
// 2x the TLP of R3) + U=16 double-buffered pipeline (16 LDG.64 = 128 B
// continuously in flight per thread -> ~4 MB chip-wide, above the
// ~2.5 MB BW*latency product). Streaming cache hints (no reuse).

static constexpr int B = 32;
static constexpr int H = 1024;
static constexpr int W = 2048;
static constexpr int W2 = W / 2;            // 1024 float2 per row
static constexpr int NCOLS = B * W2;        // 32768 threads
static constexpr int U = 16;                // float2 loads per chunk
static constexpr int NCHUNK = H / U;        // 64 chunks (even)

__global__ void __launch_bounds__(64)
cummax_h_kernel(const float2* __restrict__ x, float2* __restrict__ out) {
    int c = blockIdx.x * blockDim.x + threadIdx.x;   // 0 .. NCOLS-1

    int b  = c >> 10;          // c / 1024
    int w2 = c & (W2 - 1);     // c % 1024

    const float2* __restrict__ p = x   + (size_t)b * H * W2 + w2;
    float2*       __restrict__ q = out + (size_t)b * H * W2 + w2;

    float2 m = make_float2(-CUDART_INF_F, -CUDART_INF_F);

    float2 va[U], vb[U];

    // Prologue: load chunk 0 into va.
    #pragma unroll
    for (int i = 0; i < U; i++)
        va[i] = __ldcs(p + (size_t)i * W2);

    // Main loop: two chunks per iteration; always prefetch the next
    // chunk before consuming the current one so loads never drain.
    for (int cc = 0; cc < NCHUNK; cc += 2) {
        int hA = cc * U;
        int hB = (cc + 1) * U;
        int hC = (cc + 2) * U;

        // Prefetch chunk cc+1 into vb (NCHUNK even -> always valid).
        #pragma unroll
        for (int i = 0; i < U; i++)
            vb[i] = __ldcs(p + (size_t)(hB + i) * W2);

        // Consume chunk cc (va): dependent fmax chain + streaming stores.
        #pragma unroll
        for (int i = 0; i < U; i++) {
            m.x = fmaxf(m.x, va[i].x);
            m.y = fmaxf(m.y, va[i].y);
            __stcs(q + (size_t)(hA + i) * W2, m);
        }

        // Prefetch chunk cc+2 into va (guarded for the final iteration).
        if (cc + 2 < NCHUNK) {
            #pragma unroll
            for (int i = 0; i < U; i++)
                va[i] = __ldcs(p + (size_t)(hC + i) * W2);
        }

        // Consume chunk cc+1 (vb).
        #pragma unroll
        for (int i = 0; i < U; i++) {
            m.x = fmaxf(m.x, vb[i].x);
            m.y = fmaxf(m.y, vb[i].y);
            __stcs(q + (size_t)(hB + i) * W2, m);
        }
    }
}

extern "C" void kernel_launch(void* const* d_in, const int* in_sizes, int n_in,
                              void* d_out, int out_size) {
    const float2* x   = (const float2*)d_in[0];
    float2*       out = (float2*)d_out;

    // 512 blocks x 64 threads = 32768 threads, one per float2 column.
    cummax_h_kernel<<<NCOLS / 64, 64>>>(x, out);
}

// round 6
// speedup vs baseline: 1.5392x; 1.1106x over previous
#include <cuda_runtime.h>
#include <math_constants.h>

// Cumulative max along H for x[B=32, C=1, H=1024, W=2048] fp32.
// Single streaming pass: 256 MB read + 256 MB write (the traffic floor).
//
// R5: rolling ring-buffer software pipeline (depth U=32). Each unrolled
// step refills buf[i] with the load U rows ahead BEFORE consuming the
// old value, so SASS interleaves LDG/FMNMX/STG continuously: in-flight
// bytes per thread are pinned at U*8B = 256 B (8 MB chip-wide), with no
// drain windows between chunks. Grid 1024x32 for <=2% SM load imbalance
// (vs 16% at 512 blocks). Streaming cache hints: no byte is reused.

static constexpr int B = 32;
static constexpr int H = 1024;
static constexpr int W = 2048;
static constexpr int W2 = W / 2;            // 1024 float2 per row
static constexpr int NCOLS = B * W2;        // 32768 threads
static constexpr int U = 32;                // pipeline depth (float2 loads)
static constexpr int NCHUNK = H / U;        // 32 chunks

__global__ void __launch_bounds__(32)
cummax_h_kernel(const float2* __restrict__ x, float2* __restrict__ out) {
    int c = blockIdx.x * blockDim.x + threadIdx.x;   // 0 .. NCOLS-1

    int b  = c >> 10;          // c / 1024
    int w2 = c & (W2 - 1);     // c % 1024

    const float2* __restrict__ p = x   + (size_t)b * H * W2 + w2;
    float2*       __restrict__ q = out + (size_t)b * H * W2 + w2;

    float2 m = make_float2(-CUDART_INF_F, -CUDART_INF_F);

    float2 buf[U];

    // Prologue: fill the pipeline with chunk 0 (rows 0..U-1).
    #pragma unroll
    for (int i = 0; i < U; i++)
        buf[i] = __ldcs(p + (size_t)i * W2);

    // Steady state: consume row h0+i while refilling with row h0+i+U.
    // Refill is issued first (independent of the fmax chain) so a load
    // goes out every few instructions, keeping U loads in flight always.
    for (int cc = 0; cc < NCHUNK - 1; cc++) {
        int hCur = cc * U;
        int hNxt = hCur + U;
        #pragma unroll
        for (int i = 0; i < U; i++) {
            float2 v = buf[i];
            buf[i] = __ldcs(p + (size_t)(hNxt + i) * W2);
            m.x = fmaxf(m.x, v.x);
            m.y = fmaxf(m.y, v.y);
            __stcs(q + (size_t)(hCur + i) * W2, m);
        }
    }

    // Epilogue: drain the last chunk (rows H-U .. H-1).
    {
        int hCur = (NCHUNK - 1) * U;
        #pragma unroll
        for (int i = 0; i < U; i++) {
            m.x = fmaxf(m.x, buf[i].x);
            m.y = fmaxf(m.y, buf[i].y);
            __stcs(q + (size_t)(hCur + i) * W2, m);
        }
    }
}

extern "C" void kernel_launch(void* const* d_in, const int* in_sizes, int n_in,
                              void* d_out, int out_size) {
    const float2* x   = (const float2*)d_in[0];
    float2*       out = (float2*)d_out;

    // 1024 blocks x 32 threads = 32768 threads, one per float2 column.
    cummax_h_kernel<<<NCOLS / 32, 32>>>(x, out);
}